// round 9
// baseline (speedup 1.0000x reference)
#include <cuda_runtime.h>
#include <cstdint>

// Problem constants
#define Nn 20000
#define Ee 320000
#define Bb 2
#define INF_DIM 32
#define HIDD 64
#define HEADS 4
#define OUTD 8
#define SLOPE 0.2f

#define NB (Nn*Bb)              // 40000
#define FTC (HEADS*HIDD)        // 256

// Scratch (device globals)
__device__ __align__(16) float g_x[NB*HIDD];
__device__ __align__(16) float g_ft[(size_t)NB*FTC];
__device__ __align__(16) float g_res[NB*HIDD];
__device__ __align__(16) float g_e[(size_t)Ee*8];   // per-edge exp values, CSR order
__device__ float g_el[NB*HEADS];   // [(node*2+b)*4 + h]
__device__ float g_er[NB*HEADS];
__device__ float g_P[HIDD*8];      // [k*8 + q], q<4: Pl, q>=4: Pr
__device__ int g_deg[Nn];
__device__ int g_rowptr[Nn];
__device__ int g_col[Ee];
__device__ int g_rank[Ee];
__device__ int g_pos[Ee];
__device__ int g_total;

// ---- packed f32x2 helpers (sm_103a FFMA2) ----
__device__ __forceinline__ uint64_t pk2(float lo, float hi) {
    uint64_t r; asm("mov.b64 %0, {%1,%2};" : "=l"(r) : "f"(lo), "f"(hi)); return r;
}
__device__ __forceinline__ void fma2(uint64_t& acc, uint64_t a, uint64_t b) {
    asm("fma.rn.f32x2 %0, %1, %2, %0;" : "+l"(acc) : "l"(a), "l"(b));
}
__device__ __forceinline__ float2 upk(uint64_t v) {
    float2 r; asm("mov.b64 {%0,%1}, %2;" : "=f"(r.x), "=f"(r.y) : "l"(v)); return r;
}

// ---------------- CSR build ----------------
__global__ void zero_k() {
    int idx = blockIdx.x * blockDim.x + threadIdx.x;
    if (idx < Nn) g_deg[idx] = 0;
    if (idx == 0) g_total = 0;
}

__global__ void hist_k(const int* __restrict__ ei) {
    int idx = blockIdx.x * blockDim.x + threadIdx.x;
    if (idx < Ee) g_rank[idx] = atomicAdd(&g_deg[ei[Ee + idx]], 1);
}

// segment allocation: warp-aggregated atomic bump (order across warps arbitrary)
__global__ void alloc_k() {
    int idx = blockIdx.x * blockDim.x + threadIdx.x;
    int lane = threadIdx.x & 31;
    int d = (idx < Nn) ? g_deg[idx] : 0;
    int incl = d;
#pragma unroll
    for (int o = 1; o < 32; o <<= 1) {
        int t = __shfl_up_sync(0xffffffffu, incl, o);
        if (lane >= o) incl += t;
    }
    int wtot = __shfl_sync(0xffffffffu, incl, 31);
    int base = 0;
    if (lane == 0) base = atomicAdd(&g_total, wtot);
    base = __shfl_sync(0xffffffffu, base, 0);
    if (idx < Nn) g_rowptr[idx] = base + incl - d;
}

// atomic-free fill using precomputed ranks; also record CSR position per edge
__global__ void fill_k(const int* __restrict__ ei) {
    int idx = blockIdx.x * blockDim.x + threadIdx.x;
    if (idx >= Ee) return;
    int d = ei[Ee + idx];
    int pos = g_rowptr[d] + g_rank[idx];
    g_col[pos] = ei[idx];
    g_pos[idx] = pos;
}

// ---------------- P = reshape(W_gat)[k, h*64+d] @ a_{l,r}[h, d] ----------------
__global__ void proj_k(const float* __restrict__ W_gat, const float* __restrict__ a_l,
                       const float* __restrict__ a_r) {
    int t = threadIdx.x;          // 512 threads
    int k = t >> 3, q = t & 7;
    int h = q & 3;
    const float* a = (q < 4) ? a_l : a_r;
    float s = 0.f;
#pragma unroll
    for (int d = 0; d < HIDD; d++)
        s += W_gat[k*FTC + h*HIDD + d] * a[h*HIDD + d];
    g_P[k*8 + q] = s;
}

// ---------------- encoder ----------------
__global__ void enc_k(const float* __restrict__ h, const float* __restrict__ W_enc,
                      const float* __restrict__ b_enc) {
    int idx = blockIdx.x * blockDim.x + threadIdx.x;
    if (idx >= NB*HIDD) return;
    int d  = idx & 63;
    int nb = idx >> 6;
    int n = nb >> 1, b = nb & 1;
    const float* hr = &h[((size_t)b*Nn + n)*INF_DIM];
    float acc = b_enc[d];
#pragma unroll
    for (int k = 0; k < INF_DIM; k++) acc += hr[k] * W_enc[k*HIDD + d];
    g_x[idx] = acc;
}

// ---------------- ft = x @ W_gat, res = x @ W_res + b_res, el/er = x @ P ----------------
#define FTROWS 32
#define RP (FTROWS/2)       // 16 row-pairs
#define XPAD 17             // u64 pitch (pad)
__global__ void ft_k(const float* __restrict__ W_gat,
                     const float* __restrict__ W_res, const float* __restrict__ b_res) {
    __shared__ uint64_t xs2[HIDD * XPAD];
    __shared__ float Ps[HIDD * 8];
    int t = threadIdx.x;
    int nb0 = blockIdx.x * FTROWS;

    {
        float* xf = (float*)xs2;
        for (int i = t; i < FTROWS*HIDD; i += 256) {
            int row = i >> 6, k = i & 63;
            xf[k*(2*XPAD) + row] = g_x[(size_t)(nb0 + row)*HIDD + k];
        }
        for (int i = t; i < HIDD*8; i += 256) Ps[i] = g_P[i];
    }
    __syncthreads();

    uint64_t acc[RP];
#pragma unroll
    for (int r = 0; r < RP; r++) acc[r] = 0ull;

    for (int k = 0; k < HIDD; k++) {
        float w = W_gat[k*FTC + t];
        uint64_t w2 = pk2(w, w);
        const uint64_t* xr = &xs2[k*XPAD];
#pragma unroll
        for (int r = 0; r < RP; r++) fma2(acc[r], xr[r], w2);
    }
#pragma unroll
    for (int r = 0; r < RP; r++) {
        float2 v = upk(acc[r]);
        g_ft[((size_t)(nb0 + 2*r))*FTC + t]     = v.x;
        g_ft[((size_t)(nb0 + 2*r + 1))*FTC + t] = v.y;
    }

    // res
    {
        int c = t & 63, q = t >> 6;
        float bb = b_res[c];
        uint64_t racc[4];
#pragma unroll
        for (int i = 0; i < 4; i++) racc[i] = pk2(bb, bb);
        for (int k = 0; k < HIDD; k++) {
            float w = W_res[k*HIDD + c];
            uint64_t w2 = pk2(w, w);
            const uint64_t* xr = &xs2[k*XPAD];
#pragma unroll
            for (int i = 0; i < 4; i++) fma2(racc[i], xr[q + 4*i], w2);
        }
#pragma unroll
        for (int i = 0; i < 4; i++) {
            float2 v = upk(racc[i]);
            int rp = q + 4*i;
            g_res[(size_t)(nb0 + 2*rp)*HIDD + c]     = v.x;
            g_res[(size_t)(nb0 + 2*rp + 1)*HIDD + c] = v.y;
        }
    }

    // el/er
    {
        int r = t >> 3, q = t & 7;
        const float* xf = (const float*)xs2;
        float s = 0.f;
        for (int k = 0; k < HIDD; k++)
            s += xf[k*(2*XPAD) + r] * Ps[k*8 + q];
        int nb = nb0 + r;
        if (q < 4) g_el[nb*4 + q]       = s;
        else       g_er[nb*4 + (q - 4)] = s;
    }
}

// ---------------- per-edge exp values (CSR order), fully parallel ----------------
__global__ void edge_e_k(const int* __restrict__ ei) {
    int idx = blockIdx.x * blockDim.x + threadIdx.x;
    if (idx >= Ee*8) return;
    int e = idx >> 3, q = idx & 7;
    int s = ei[e], d = ei[Ee + e];
    float v = g_el[s*8 + q] + g_er[d*8 + q];
    v = v > 0.f ? v : SLOPE * v;
    g_e[(size_t)g_pos[e]*8 + q] = __expf(v);
}

// ---------------- fused node-centric GAT aggregation + update (+ optional decoder) ----------------
// one warp per dst node, both batches. e-values preloaded (coalesced), so the
// hot loop is pure shfl + LDG.128 gather + FFMA2 with no exp/scatter chain.
__global__ void node_agg_k(const float* __restrict__ b_gat,
                           const float* __restrict__ W_dec, const float* __restrict__ b_dec,
                           float* __restrict__ out, int last) {
    int w = (blockIdx.x * blockDim.x + threadIdx.x) >> 5;
    int lane = threadIdx.x & 31;
    if (w >= Nn) return;
    int beg = g_rowptr[w];
    int end = beg + g_deg[w];

    int b   = lane >> 4;               // gather role: batch
    int l16 = lane & 15;               // gather role: dim-quad
    int eL  = lane >> 1;               // e-load role: edge slot in 16-edge phase
    int ebq = (lane & 1) * 4;          // e-load role: batch quad offset

    float4 zacc = make_float4(0.f, 0.f, 0.f, 0.f);
    uint64_t acc2[HEADS][2];
#pragma unroll
    for (int h = 0; h < HEADS; h++) { acc2[h][0] = 0ull; acc2[h][1] = 0ull; }

    int i0 = beg;
    // main phases: 16 edges, straight-line
    for (; i0 + 16 <= end; i0 += 16) {
        int sl = (lane < 16) ? g_col[i0 + lane] : 0;
        float4 ev = *(const float4*)&g_e[(size_t)(i0 + eL)*8 + ebq];
        zacc.x += ev.x; zacc.y += ev.y; zacc.z += ev.z; zacc.w += ev.w;
#pragma unroll
        for (int j = 0; j < 16; j++) {
            int s = __shfl_sync(0xffffffffu, sl, j);
            int src = j*2 + b;
            float a0 = __shfl_sync(0xffffffffu, ev.x, src);
            float a1 = __shfl_sync(0xffffffffu, ev.y, src);
            float a2 = __shfl_sync(0xffffffffu, ev.z, src);
            float a3 = __shfl_sync(0xffffffffu, ev.w, src);
            uint64_t A0 = pk2(a0, a0), A1 = pk2(a1, a1);
            uint64_t A2 = pk2(a2, a2), A3 = pk2(a3, a3);
            const ulonglong2* f = (const ulonglong2*)&g_ft[((size_t)(s*2 + b))*FTC];
            ulonglong2 v0 = f[l16];
            ulonglong2 v1 = f[16 + l16];
            ulonglong2 v2 = f[32 + l16];
            ulonglong2 v3 = f[48 + l16];
            fma2(acc2[0][0], v0.x, A0); fma2(acc2[0][1], v0.y, A0);
            fma2(acc2[1][0], v1.x, A1); fma2(acc2[1][1], v1.y, A1);
            fma2(acc2[2][0], v2.x, A2); fma2(acc2[2][1], v2.y, A2);
            fma2(acc2[3][0], v3.x, A3); fma2(acc2[3][1], v3.y, A3);
        }
    }
    // tail phase: <16 edges, predicated
    if (i0 < end) {
        int nE = end - i0;
        int sl = (lane < 16 && i0 + lane < end) ? g_col[i0 + lane] : 0;
        float4 ev = make_float4(0.f, 0.f, 0.f, 0.f);
        if (i0 + eL < end)
            ev = *(const float4*)&g_e[(size_t)(i0 + eL)*8 + ebq];
        zacc.x += ev.x; zacc.y += ev.y; zacc.z += ev.z; zacc.w += ev.w;
        for (int j = 0; j < nE; j++) {
            int s = __shfl_sync(0xffffffffu, sl, j);
            int src = j*2 + b;
            float a0 = __shfl_sync(0xffffffffu, ev.x, src);
            float a1 = __shfl_sync(0xffffffffu, ev.y, src);
            float a2 = __shfl_sync(0xffffffffu, ev.z, src);
            float a3 = __shfl_sync(0xffffffffu, ev.w, src);
            uint64_t A0 = pk2(a0, a0), A1 = pk2(a1, a1);
            uint64_t A2 = pk2(a2, a2), A3 = pk2(a3, a3);
            const ulonglong2* f = (const ulonglong2*)&g_ft[((size_t)(s*2 + b))*FTC];
            ulonglong2 v0 = f[l16];
            ulonglong2 v1 = f[16 + l16];
            ulonglong2 v2 = f[32 + l16];
            ulonglong2 v3 = f[48 + l16];
            fma2(acc2[0][0], v0.x, A0); fma2(acc2[0][1], v0.y, A0);
            fma2(acc2[1][0], v1.x, A1); fma2(acc2[1][1], v1.y, A1);
            fma2(acc2[2][0], v2.x, A2); fma2(acc2[2][1], v2.y, A2);
            fma2(acc2[3][0], v3.x, A3); fma2(acc2[3][1], v3.y, A3);
        }
    }

    // z reduce across lanes of same parity (parity == e-load batch)
#pragma unroll
    for (int o = 2; o < 32; o <<= 1) {
        zacc.x += __shfl_xor_sync(0xffffffffu, zacc.x, o);
        zacc.y += __shfl_xor_sync(0xffffffffu, zacc.y, o);
        zacc.z += __shfl_xor_sync(0xffffffffu, zacc.z, o);
        zacc.w += __shfl_xor_sync(0xffffffffu, zacc.w, o);
    }
    // lane b (0 or 1) now holds z[b][h]; fetch own batch's z
    float4 zb;
    zb.x = __shfl_sync(0xffffffffu, zacc.x, b);
    zb.y = __shfl_sync(0xffffffffu, zacc.y, b);
    zb.z = __shfl_sync(0xffffffffu, zacc.z, b);
    zb.w = __shfl_sync(0xffffffffu, zacc.w, b);

    // normalize + head-mean
    float rz[4];
    rz[0] = (zb.x > 0.f) ? 0.25f / zb.x : 0.f;
    rz[1] = (zb.y > 0.f) ? 0.25f / zb.y : 0.f;
    rz[2] = (zb.z > 0.f) ? 0.25f / zb.z : 0.f;
    rz[3] = (zb.w > 0.f) ? 0.25f / zb.w : 0.f;
    float4 o = make_float4(0.f, 0.f, 0.f, 0.f);
#pragma unroll
    for (int h = 0; h < HEADS; h++) {
        float2 p = upk(acc2[h][0]);
        float2 q = upk(acc2[h][1]);
        o.x += p.x * rz[h]; o.y += p.y * rz[h];
        o.z += q.x * rz[h]; o.w += q.y * rz[h];
    }

    // epilogue: + mean_h(b_gat) + res, ELU
    int d0 = l16 * 4;
    const float4* bg = (const float4*)b_gat;
    float4 b0 = bg[l16], b1 = bg[16 + l16], b2 = bg[32 + l16], b3 = bg[48 + l16];
    float4 bgm;
    bgm.x = 0.25f*(b0.x + b1.x + b2.x + b3.x);
    bgm.y = 0.25f*(b0.y + b1.y + b2.y + b3.y);
    bgm.z = 0.25f*(b0.z + b1.z + b2.z + b3.z);
    bgm.w = 0.25f*(b0.w + b1.w + b2.w + b3.w);

    float4 rv = *(const float4*)&g_res[((size_t)(w*2 + b))*HIDD + d0];
    float ox = o.x + bgm.x + rv.x;
    float oy = o.y + bgm.y + rv.y;
    float oz = o.z + bgm.z + rv.z;
    float ow = o.w + bgm.w + rv.w;
    ox = ox > 0.f ? ox : expm1f(ox);
    oy = oy > 0.f ? oy : expm1f(oy);
    oz = oz > 0.f ? oz : expm1f(oz);
    ow = ow > 0.f ? ow : expm1f(ow);

    if (!last) {
        *(float4*)&g_x[((size_t)(w*2 + b))*HIDD + d0] = make_float4(ox, oy, oz, ow);
    } else {
        // fused decoder: out[b, w, :] = x[w, b, :] @ W_dec + b_dec
        float po[OUTD];
        const float4* W0 = (const float4*)&W_dec[(d0 + 0)*OUTD];
        const float4* W1 = (const float4*)&W_dec[(d0 + 1)*OUTD];
        const float4* W2 = (const float4*)&W_dec[(d0 + 2)*OUTD];
        const float4* W3 = (const float4*)&W_dec[(d0 + 3)*OUTD];
        float4 wa, wb;
        wa = W0[0]; wb = W0[1];
        po[0] = ox*wa.x; po[1] = ox*wa.y; po[2] = ox*wa.z; po[3] = ox*wa.w;
        po[4] = ox*wb.x; po[5] = ox*wb.y; po[6] = ox*wb.z; po[7] = ox*wb.w;
        wa = W1[0]; wb = W1[1];
        po[0] += oy*wa.x; po[1] += oy*wa.y; po[2] += oy*wa.z; po[3] += oy*wa.w;
        po[4] += oy*wb.x; po[5] += oy*wb.y; po[6] += oy*wb.z; po[7] += oy*wb.w;
        wa = W2[0]; wb = W2[1];
        po[0] += oz*wa.x; po[1] += oz*wa.y; po[2] += oz*wa.z; po[3] += oz*wa.w;
        po[4] += oz*wb.x; po[5] += oz*wb.y; po[6] += oz*wb.z; po[7] += oz*wb.w;
        wa = W3[0]; wb = W3[1];
        po[0] += ow*wa.x; po[1] += ow*wa.y; po[2] += ow*wa.z; po[3] += ow*wa.w;
        po[4] += ow*wb.x; po[5] += ow*wb.y; po[6] += ow*wb.z; po[7] += ow*wb.w;
#pragma unroll
        for (int off = 1; off < 16; off <<= 1)
#pragma unroll
            for (int oo = 0; oo < OUTD; oo++)
                po[oo] += __shfl_xor_sync(0xffffffffu, po[oo], off);
        if (l16 == 0) {
            float* op = &out[((size_t)b*Nn + w)*OUTD];
            float4 v0 = make_float4(po[0] + b_dec[0], po[1] + b_dec[1],
                                    po[2] + b_dec[2], po[3] + b_dec[3]);
            float4 v1 = make_float4(po[4] + b_dec[4], po[5] + b_dec[5],
                                    po[6] + b_dec[6], po[7] + b_dec[7]);
            *(float4*)&op[0] = v0;
            *(float4*)&op[4] = v1;
        }
    }
}

extern "C" void kernel_launch(void* const* d_in, const int* in_sizes, int n_in,
                              void* d_out, int out_size) {
    const float* h     = (const float*)d_in[0];
    const int*   ei    = (const int*)  d_in[1];
    const float* W_enc = (const float*)d_in[2];
    const float* b_enc = (const float*)d_in[3];
    const float* W_gat = (const float*)d_in[4];
    const float* a_l   = (const float*)d_in[5];
    const float* a_r   = (const float*)d_in[6];
    const float* b_gat = (const float*)d_in[7];
    const float* W_res = (const float*)d_in[8];
    const float* b_res = (const float*)d_in[9];
    const float* W_dec = (const float*)d_in[10];
    const float* b_dec = (const float*)d_in[11];
    float* out = (float*)d_out;

    // CSR build (every call; graph-replay safe)
    zero_k<<<(Nn + 255)/256, 256>>>();
    hist_k<<<(Ee + 255)/256, 256>>>(ei);
    alloc_k<<<(Nn + 255)/256, 256>>>();
    fill_k<<<(Ee + 255)/256, 256>>>(ei);

    proj_k<<<1, 512>>>(W_gat, a_l, a_r);
    enc_k<<<(NB*HIDD + 255)/256, 256>>>(h, W_enc, b_enc);

    for (int it = 0; it < 2; ++it) {
        ft_k<<<NB/FTROWS, 256>>>(W_gat, W_res, b_res);
        edge_e_k<<<(Ee*8 + 255)/256, 256>>>(ei);
        node_agg_k<<<(Nn*32 + 255)/256, 256>>>(b_gat, W_dec, b_dec, out, it == 1);
    }
}

// round 10
// speedup vs baseline: 1.3757x; 1.3757x over previous
#include <cuda_runtime.h>
#include <cuda_fp16.h>
#include <cstdint>

// Problem constants
#define Nn 20000
#define Ee 320000
#define Bb 2
#define INF_DIM 32
#define HIDD 64
#define HEADS 4
#define OUTD 8
#define SLOPE 0.2f

#define NB (Nn*Bb)              // 40000
#define FTC (HEADS*HIDD)        // 256

// Scratch (device globals)
__device__ __align__(16) float g_x[NB*HIDD];
__device__ __align__(16) __half g_fth[(size_t)NB*FTC];   // ft in fp16
__device__ __align__(16) float g_res[NB*HIDD];
__device__ float g_el[NB*HEADS];   // [(node*2+b)*4 + h]
__device__ float g_er[NB*HEADS];
__device__ float g_P[HIDD*8];      // [k*8 + q], q<4: Pl, q>=4: Pr
__device__ int g_deg[Nn];
__device__ int g_rowptr[Nn];
__device__ int g_col[Ee];
__device__ int g_rank[Ee];
__device__ int g_total;

// ---- packed f32x2 helpers (sm_103a FFMA2) ----
__device__ __forceinline__ uint64_t pk2(float lo, float hi) {
    uint64_t r; asm("mov.b64 %0, {%1,%2};" : "=l"(r) : "f"(lo), "f"(hi)); return r;
}
__device__ __forceinline__ void fma2(uint64_t& acc, uint64_t a, uint64_t b) {
    asm("fma.rn.f32x2 %0, %1, %2, %0;" : "+l"(acc) : "l"(a), "l"(b));
}
__device__ __forceinline__ float2 upk(uint64_t v) {
    float2 r; asm("mov.b64 {%0,%1}, %2;" : "=f"(r.x), "=f"(r.y) : "l"(v)); return r;
}

// ---------------- CSR build ----------------
__global__ void zero_k() {
    int idx = blockIdx.x * blockDim.x + threadIdx.x;
    if (idx < Nn) g_deg[idx] = 0;
    if (idx == 0) g_total = 0;
}

__global__ void hist_k(const int* __restrict__ ei) {
    int idx = blockIdx.x * blockDim.x + threadIdx.x;
    if (idx < Ee) g_rank[idx] = atomicAdd(&g_deg[ei[Ee + idx]], 1);
}

// segment allocation: warp-aggregated atomic bump (order across warps arbitrary)
__global__ void alloc_k() {
    int idx = blockIdx.x * blockDim.x + threadIdx.x;
    int lane = threadIdx.x & 31;
    int d = (idx < Nn) ? g_deg[idx] : 0;
    int incl = d;
#pragma unroll
    for (int o = 1; o < 32; o <<= 1) {
        int t = __shfl_up_sync(0xffffffffu, incl, o);
        if (lane >= o) incl += t;
    }
    int wtot = __shfl_sync(0xffffffffu, incl, 31);
    int base = 0;
    if (lane == 0) base = atomicAdd(&g_total, wtot);
    base = __shfl_sync(0xffffffffu, base, 0);
    if (idx < Nn) g_rowptr[idx] = base + incl - d;
}

// atomic-free fill using precomputed ranks
__global__ void fill_k(const int* __restrict__ ei) {
    int idx = blockIdx.x * blockDim.x + threadIdx.x;
    if (idx >= Ee) return;
    int d = ei[Ee + idx];
    g_col[g_rowptr[d] + g_rank[idx]] = ei[idx];
}

// ---------------- P = reshape(W_gat)[k, h*64+d] @ a_{l,r}[h, d] ----------------
__global__ void proj_k(const float* __restrict__ W_gat, const float* __restrict__ a_l,
                       const float* __restrict__ a_r) {
    int t = threadIdx.x;          // 512 threads
    int k = t >> 3, q = t & 7;
    int h = q & 3;
    const float* a = (q < 4) ? a_l : a_r;
    float s = 0.f;
#pragma unroll
    for (int d = 0; d < HIDD; d++)
        s += W_gat[k*FTC + h*HIDD + d] * a[h*HIDD + d];
    g_P[k*8 + q] = s;
}

// ---------------- encoder ----------------
__global__ void enc_k(const float* __restrict__ h, const float* __restrict__ W_enc,
                      const float* __restrict__ b_enc) {
    int idx = blockIdx.x * blockDim.x + threadIdx.x;
    if (idx >= NB*HIDD) return;
    int d  = idx & 63;
    int nb = idx >> 6;
    int n = nb >> 1, b = nb & 1;
    const float* hr = &h[((size_t)b*Nn + n)*INF_DIM];
    float acc = b_enc[d];
#pragma unroll
    for (int k = 0; k < INF_DIM; k++) acc += hr[k] * W_enc[k*HIDD + d];
    g_x[idx] = acc;
}

// ---------------- ft = x @ W_gat (fp16), res = x @ W_res + b_res, el/er = x @ P ----------------
// 256 threads, 32 rows/block. x transposed row-paired in smem.
// Main GEMM: thread owns COLUMN PAIR (2ch, 2ch+1) and 8 row-pairs (half rh):
// per k: 1 LDG.64 + 8 LDS.64 + 16 FFMA2  (2x less LDS traffic per FMA than 1-col version)
#define FTROWS 32
#define XPAD 17             // u64 pitch (pad)
__global__ void ft_k(const float* __restrict__ W_gat,
                     const float* __restrict__ W_res, const float* __restrict__ b_res) {
    __shared__ uint64_t xs2[HIDD * XPAD];
    __shared__ float Ps[HIDD * 8];
    int t = threadIdx.x;
    int nb0 = blockIdx.x * FTROWS;

    {
        float* xf = (float*)xs2;
        for (int i = t; i < FTROWS*HIDD; i += 256) {
            int row = i >> 6, k = i & 63;
            xf[k*(2*XPAD) + row] = g_x[(size_t)(nb0 + row)*HIDD + k];
        }
        for (int i = t; i < HIDD*8; i += 256) Ps[i] = g_P[i];
    }
    __syncthreads();

    // main GEMM
    {
        int ch = t & 127;          // column pair index: cols 2ch, 2ch+1
        int rh = t >> 7;           // row half: row-pairs rh*8 .. rh*8+7
        uint64_t acc0[8], acc1[8];
#pragma unroll
        for (int r = 0; r < 8; r++) { acc0[r] = 0ull; acc1[r] = 0ull; }

        for (int k = 0; k < HIDD; k++) {
            float2 w = *(const float2*)&W_gat[k*FTC + ch*2];
            uint64_t w0 = pk2(w.x, w.x);
            uint64_t w1 = pk2(w.y, w.y);
            const uint64_t* xr = &xs2[k*XPAD + rh*8];
#pragma unroll
            for (int r = 0; r < 8; r++) {
                fma2(acc0[r], xr[r], w0);
                fma2(acc1[r], xr[r], w1);
            }
        }
#pragma unroll
        for (int r = 0; r < 8; r++) {
            float2 va = upk(acc0[r]);   // col 2ch,   rows {even, odd}
            float2 vb = upk(acc1[r]);   // col 2ch+1, rows {even, odd}
            int rp = rh*8 + r;
            *(__half2*)&g_fth[((size_t)(nb0 + 2*rp))*FTC + ch*2]     = __floats2half2_rn(va.x, vb.x);
            *(__half2*)&g_fth[((size_t)(nb0 + 2*rp + 1))*FTC + ch*2] = __floats2half2_rn(va.y, vb.y);
        }
    }

    // res: thread owns col pair (2cr, 2cr+1), row-pair group rr (2 row-pairs)
    {
        int cr = t & 31;           // cols 2cr, 2cr+1
        int rr = t >> 5;           // row-pairs rr*2, rr*2+1
        float2 bb = *(const float2*)&b_res[cr*2];
        uint64_t a0[2], a1[2];
        a0[0] = pk2(bb.x, bb.x); a0[1] = a0[0];
        a1[0] = pk2(bb.y, bb.y); a1[1] = a1[0];
        for (int k = 0; k < HIDD; k++) {
            float2 w = *(const float2*)&W_res[k*HIDD + cr*2];
            uint64_t w0 = pk2(w.x, w.x);
            uint64_t w1 = pk2(w.y, w.y);
            const uint64_t* xr = &xs2[k*XPAD + rr*2];
            fma2(a0[0], xr[0], w0); fma2(a1[0], xr[0], w1);
            fma2(a0[1], xr[1], w0); fma2(a1[1], xr[1], w1);
        }
#pragma unroll
        for (int i = 0; i < 2; i++) {
            float2 va = upk(a0[i]);
            float2 vb = upk(a1[i]);
            int rp = rr*2 + i;
            *(float2*)&g_res[(size_t)(nb0 + 2*rp)*HIDD + cr*2]     = make_float2(va.x, vb.x);
            *(float2*)&g_res[(size_t)(nb0 + 2*rp + 1)*HIDD + cr*2] = make_float2(va.y, vb.y);
        }
    }

    // el/er: thread t -> row r = t>>3 (0..31), q = t&7
    {
        int r = t >> 3, q = t & 7;
        const float* xf = (const float*)xs2;
        float s = 0.f;
        for (int k = 0; k < HIDD; k++)
            s += xf[k*(2*XPAD) + r] * Ps[k*8 + q];
        int nb = nb0 + r;
        if (q < 4) g_el[nb*4 + q]       = s;
        else       g_er[nb*4 + (q - 4)] = s;
    }
}

// ---------------- fused node-centric GAT aggregation + update (+ optional decoder) ----------------
// one warp per dst node, both batches. 4 edges' e-values computed in parallel.
// Gather in fp16 (uint2 = 4 dims per head), accumulate fp32. (R7 structure — best known.)
__global__ void node_agg_k(const float* __restrict__ b_gat,
                           const float* __restrict__ W_dec, const float* __restrict__ b_dec,
                           float* __restrict__ out, int last) {
    int w = (blockIdx.x * blockDim.x + threadIdx.x) >> 5;
    int lane = threadIdx.x & 31;
    if (w >= Nn) return;
    int beg = g_rowptr[w];
    int end = beg + g_deg[w];

    int bh = lane & 7;                 // e-computation role
    int b  = lane >> 4;                // gather role: batch
    int l16 = lane & 15;               // gather role: dim-quad

    float er_v = (lane < 8) ? g_er[w*8 + lane] : 0.f;
    float er_mine = __shfl_sync(0xffffffffu, er_v, bh);

    float zpart = 0.f;
    float4 acc[HEADS];
#pragma unroll
    for (int h = 0; h < HEADS; h++) acc[h] = make_float4(0.f, 0.f, 0.f, 0.f);

    for (int i0 = beg; i0 < end; i0 += 32) {
        int sj = (i0 + lane < end) ? g_col[i0 + lane] : 0;
        int nE = end - i0; if (nE > 32) nE = 32;
        for (int g = 0; g < nE; g += 4) {
            int slot = lane >> 3;
            int s4 = __shfl_sync(0xffffffffu, sj, g + slot);
            bool valid = (g + slot) < nE;
            float e = 0.f;
            if (valid) {
                float v = g_el[s4*8 + bh] + er_mine;
                v = v > 0.f ? v : SLOPE * v;
                e = __expf(v);
            }
            zpart += e;

            int nG = nE - g; if (nG > 4) nG = 4;
#pragma unroll
            for (int gg = 0; gg < 4; gg++) {
                if (gg >= nG) break;
                int s = __shfl_sync(0xffffffffu, sj, g + gg);
                float a0 = __shfl_sync(0xffffffffu, e, gg*8 + b*4 + 0);
                float a1 = __shfl_sync(0xffffffffu, e, gg*8 + b*4 + 1);
                float a2 = __shfl_sync(0xffffffffu, e, gg*8 + b*4 + 2);
                float a3 = __shfl_sync(0xffffffffu, e, gg*8 + b*4 + 3);
                const uint2* f = (const uint2*)&g_fth[((size_t)(s*2 + b))*FTC];
                uint2 u0 = f[l16];
                uint2 u1 = f[16 + l16];
                uint2 u2 = f[32 + l16];
                uint2 u3 = f[48 + l16];
                float2 p, q;
                p = __half22float2(*(__half2*)&u0.x); q = __half22float2(*(__half2*)&u0.y);
                acc[0].x += a0*p.x; acc[0].y += a0*p.y; acc[0].z += a0*q.x; acc[0].w += a0*q.y;
                p = __half22float2(*(__half2*)&u1.x); q = __half22float2(*(__half2*)&u1.y);
                acc[1].x += a1*p.x; acc[1].y += a1*p.y; acc[1].z += a1*q.x; acc[1].w += a1*q.y;
                p = __half22float2(*(__half2*)&u2.x); q = __half22float2(*(__half2*)&u2.y);
                acc[2].x += a2*p.x; acc[2].y += a2*p.y; acc[2].z += a2*q.x; acc[2].w += a2*q.y;
                p = __half22float2(*(__half2*)&u3.x); q = __half22float2(*(__half2*)&u3.y);
                acc[3].x += a3*p.x; acc[3].y += a3*p.y; acc[3].z += a3*q.x; acc[3].w += a3*q.y;
            }
        }
    }

    // z reduce: sum over the 4 edge-slots -> lane holds z for its bh
    zpart += __shfl_xor_sync(0xffffffffu, zpart, 8);
    zpart += __shfl_xor_sync(0xffffffffu, zpart, 16);

    // normalize + head-mean
    float4 o = make_float4(0.f, 0.f, 0.f, 0.f);
#pragma unroll
    for (int h = 0; h < HEADS; h++) {
        float zh = __shfl_sync(0xffffffffu, zpart, b*4 + h);
        float rz = (zh > 0.f) ? 0.25f / zh : 0.f;
        o.x += acc[h].x * rz; o.y += acc[h].y * rz;
        o.z += acc[h].z * rz; o.w += acc[h].w * rz;
    }

    // epilogue: + mean_h(b_gat) + res, ELU
    int d0 = l16 * 4;
    const float4* bg = (const float4*)b_gat;
    float4 b0 = bg[l16], b1 = bg[16 + l16], b2 = bg[32 + l16], b3 = bg[48 + l16];
    float4 bgm;
    bgm.x = 0.25f*(b0.x + b1.x + b2.x + b3.x);
    bgm.y = 0.25f*(b0.y + b1.y + b2.y + b3.y);
    bgm.z = 0.25f*(b0.z + b1.z + b2.z + b3.z);
    bgm.w = 0.25f*(b0.w + b1.w + b2.w + b3.w);

    float4 rv = *(const float4*)&g_res[((size_t)(w*2 + b))*HIDD + d0];
    float ox = o.x + bgm.x + rv.x;
    float oy = o.y + bgm.y + rv.y;
    float oz = o.z + bgm.z + rv.z;
    float ow = o.w + bgm.w + rv.w;
    ox = ox > 0.f ? ox : expm1f(ox);
    oy = oy > 0.f ? oy : expm1f(oy);
    oz = oz > 0.f ? oz : expm1f(oz);
    ow = ow > 0.f ? ow : expm1f(ow);

    if (!last) {
        *(float4*)&g_x[((size_t)(w*2 + b))*HIDD + d0] = make_float4(ox, oy, oz, ow);
    } else {
        // fused decoder: out[b, w, :] = x[w, b, :] @ W_dec + b_dec
        float po[OUTD];
        const float4* W0 = (const float4*)&W_dec[(d0 + 0)*OUTD];
        const float4* W1 = (const float4*)&W_dec[(d0 + 1)*OUTD];
        const float4* W2 = (const float4*)&W_dec[(d0 + 2)*OUTD];
        const float4* W3 = (const float4*)&W_dec[(d0 + 3)*OUTD];
        float4 wa, wb;
        wa = W0[0]; wb = W0[1];
        po[0] = ox*wa.x; po[1] = ox*wa.y; po[2] = ox*wa.z; po[3] = ox*wa.w;
        po[4] = ox*wb.x; po[5] = ox*wb.y; po[6] = ox*wb.z; po[7] = ox*wb.w;
        wa = W1[0]; wb = W1[1];
        po[0] += oy*wa.x; po[1] += oy*wa.y; po[2] += oy*wa.z; po[3] += oy*wa.w;
        po[4] += oy*wb.x; po[5] += oy*wb.y; po[6] += oy*wb.z; po[7] += oy*wb.w;
        wa = W2[0]; wb = W2[1];
        po[0] += oz*wa.x; po[1] += oz*wa.y; po[2] += oz*wa.z; po[3] += oz*wa.w;
        po[4] += oz*wb.x; po[5] += oz*wb.y; po[6] += oz*wb.z; po[7] += oz*wb.w;
        wa = W3[0]; wb = W3[1];
        po[0] += ow*wa.x; po[1] += ow*wa.y; po[2] += ow*wa.z; po[3] += ow*wa.w;
        po[4] += ow*wb.x; po[5] += ow*wb.y; po[6] += ow*wb.z; po[7] += ow*wb.w;
#pragma unroll
        for (int off = 1; off < 16; off <<= 1)
#pragma unroll
            for (int oo = 0; oo < OUTD; oo++)
                po[oo] += __shfl_xor_sync(0xffffffffu, po[oo], off);
        if (l16 == 0) {
            float* op = &out[((size_t)b*Nn + w)*OUTD];
            float4 v0 = make_float4(po[0] + b_dec[0], po[1] + b_dec[1],
                                    po[2] + b_dec[2], po[3] + b_dec[3]);
            float4 v1 = make_float4(po[4] + b_dec[4], po[5] + b_dec[5],
                                    po[6] + b_dec[6], po[7] + b_dec[7]);
            *(float4*)&op[0] = v0;
            *(float4*)&op[4] = v1;
        }
    }
}

extern "C" void kernel_launch(void* const* d_in, const int* in_sizes, int n_in,
                              void* d_out, int out_size) {
    const float* h     = (const float*)d_in[0];
    const int*   ei    = (const int*)  d_in[1];
    const float* W_enc = (const float*)d_in[2];
    const float* b_enc = (const float*)d_in[3];
    const float* W_gat = (const float*)d_in[4];
    const float* a_l   = (const float*)d_in[5];
    const float* a_r   = (const float*)d_in[6];
    const float* b_gat = (const float*)d_in[7];
    const float* W_res = (const float*)d_in[8];
    const float* b_res = (const float*)d_in[9];
    const float* W_dec = (const float*)d_in[10];
    const float* b_dec = (const float*)d_in[11];
    float* out = (float*)d_out;

    // CSR build (every call; graph-replay safe)
    zero_k<<<(Nn + 255)/256, 256>>>();
    hist_k<<<(Ee + 255)/256, 256>>>(ei);
    alloc_k<<<(Nn + 255)/256, 256>>>();
    fill_k<<<(Ee + 255)/256, 256>>>(ei);

    proj_k<<<1, 512>>>(W_gat, a_l, a_r);
    enc_k<<<(NB*HIDD + 255)/256, 256>>>(h, W_enc, b_enc);

    for (int it = 0; it < 2; ++it) {
        ft_k<<<NB/FTROWS, 256>>>(W_gat, W_res, b_res);
        node_agg_k<<<(Nn*32 + 255)/256, 256>>>(b_gat, W_dec, b_dec, out, it == 1);
    }
}

// round 11
// speedup vs baseline: 1.4472x; 1.0520x over previous
#include <cuda_runtime.h>
#include <cuda_fp16.h>
#include <cstdint>

// Problem constants
#define Nn 20000
#define Ee 320000
#define Bb 2
#define INF_DIM 32
#define HIDD 64
#define HEADS 4
#define OUTD 8
#define SLOPE 0.2f

#define NB (Nn*Bb)              // 40000
#define FTC (HEADS*HIDD)        // 256

// Scratch (device globals)
__device__ __align__(16) float g_x[NB*HIDD];
__device__ __align__(16) __half g_fth[(size_t)NB*FTC];   // ft in fp16
__device__ __align__(16) float g_res[NB*HIDD];
__device__ float g_el[NB*HEADS];   // [(node*2+b)*4 + h]
__device__ float g_er[NB*HEADS];
__device__ float g_P[HIDD*8];      // [k*8 + q], q<4: Pl, q>=4: Pr
__device__ int g_deg[Nn];
__device__ int g_rowptr[Nn];
__device__ int g_col[Ee];
__device__ int g_rank[Ee];
__device__ int g_total;

// ---- packed f32x2 helpers (sm_103a FFMA2) ----
__device__ __forceinline__ uint64_t pk2(float lo, float hi) {
    uint64_t r; asm("mov.b64 %0, {%1,%2};" : "=l"(r) : "f"(lo), "f"(hi)); return r;
}
__device__ __forceinline__ void fma2(uint64_t& acc, uint64_t a, uint64_t b) {
    asm("fma.rn.f32x2 %0, %1, %2, %0;" : "+l"(acc) : "l"(a), "l"(b));
}
__device__ __forceinline__ float2 upk(uint64_t v) {
    float2 r; asm("mov.b64 {%0,%1}, %2;" : "=f"(r.x), "=f"(r.y) : "l"(v)); return r;
}

// ---------------- CSR build ----------------
__global__ void zero_k() {
    int idx = blockIdx.x * blockDim.x + threadIdx.x;
    if (idx < Nn) g_deg[idx] = 0;
    if (idx == 0) g_total = 0;
}

__global__ void hist_k(const int* __restrict__ ei) {
    int idx = blockIdx.x * blockDim.x + threadIdx.x;
    if (idx < Ee) g_rank[idx] = atomicAdd(&g_deg[ei[Ee + idx]], 1);
}

__global__ void alloc_k() {
    int idx = blockIdx.x * blockDim.x + threadIdx.x;
    int lane = threadIdx.x & 31;
    int d = (idx < Nn) ? g_deg[idx] : 0;
    int incl = d;
#pragma unroll
    for (int o = 1; o < 32; o <<= 1) {
        int t = __shfl_up_sync(0xffffffffu, incl, o);
        if (lane >= o) incl += t;
    }
    int wtot = __shfl_sync(0xffffffffu, incl, 31);
    int base = 0;
    if (lane == 0) base = atomicAdd(&g_total, wtot);
    base = __shfl_sync(0xffffffffu, base, 0);
    if (idx < Nn) g_rowptr[idx] = base + incl - d;
}

__global__ void fill_k(const int* __restrict__ ei) {
    int idx = blockIdx.x * blockDim.x + threadIdx.x;
    if (idx >= Ee) return;
    int d = ei[Ee + idx];
    g_col[g_rowptr[d] + g_rank[idx]] = ei[idx];
}

// ---------------- P = reshape(W_gat)[k, h*64+d] @ a_{l,r}[h, d] ----------------
__global__ void proj_k(const float* __restrict__ W_gat, const float* __restrict__ a_l,
                       const float* __restrict__ a_r) {
    int t = threadIdx.x;          // 512 threads
    int k = t >> 3, q = t & 7;
    int h = q & 3;
    const float* a = (q < 4) ? a_l : a_r;
    float s = 0.f;
#pragma unroll
    for (int d = 0; d < HIDD; d++)
        s += W_gat[k*FTC + h*HIDD + d] * a[h*HIDD + d];
    g_P[k*8 + q] = s;
}

// ---------------- encoder ----------------
__global__ void enc_k(const float* __restrict__ h, const float* __restrict__ W_enc,
                      const float* __restrict__ b_enc) {
    int idx = blockIdx.x * blockDim.x + threadIdx.x;
    if (idx >= NB*HIDD) return;
    int d  = idx & 63;
    int nb = idx >> 6;
    int n = nb >> 1, b = nb & 1;
    const float* hr = &h[((size_t)b*Nn + n)*INF_DIM];
    float acc = b_enc[d];
#pragma unroll
    for (int k = 0; k < INF_DIM; k++) acc += hr[k] * W_enc[k*HIDD + d];
    g_x[idx] = acc;
}

// ---------------- ft = x @ W_gat (fp16), res = x @ W_res + b_res, el/er = x @ P ----------------
// 256 threads, 32 rows/block. x transposed row-paired in smem.
// Main GEMM: thread owns COLUMN QUAD (4cq..4cq+3) and 4 row-pairs:
// per k: 1 LDG.128 + 4 LDS.64 + 16 FFMA2
#define FTROWS 32
#define XPAD 17             // u64 pitch (pad)
__global__ void ft_k(const float* __restrict__ W_gat,
                     const float* __restrict__ W_res, const float* __restrict__ b_res) {
    __shared__ uint64_t xs2[HIDD * XPAD];
    __shared__ float Ps[HIDD * 8];
    int t = threadIdx.x;
    int nb0 = blockIdx.x * FTROWS;

    {
        float* xf = (float*)xs2;
        for (int i = t; i < FTROWS*HIDD; i += 256) {
            int row = i >> 6, k = i & 63;
            xf[k*(2*XPAD) + row] = g_x[(size_t)(nb0 + row)*HIDD + k];
        }
        for (int i = t; i < HIDD*8; i += 256) Ps[i] = g_P[i];
    }
    __syncthreads();

    // main GEMM: col-quad x 4 row-pairs
    {
        int cq = t & 63;           // cols 4cq .. 4cq+3
        int rh = t >> 6;           // row-pairs rh*4 .. rh*4+3
        uint64_t acc[4][4];        // [col][row-pair]
#pragma unroll
        for (int c = 0; c < 4; c++)
#pragma unroll
            for (int r = 0; r < 4; r++) acc[c][r] = 0ull;

        for (int k = 0; k < HIDD; k++) {
            float4 w = *(const float4*)&W_gat[k*FTC + cq*4];
            uint64_t w0 = pk2(w.x, w.x);
            uint64_t w1 = pk2(w.y, w.y);
            uint64_t w2 = pk2(w.z, w.z);
            uint64_t w3 = pk2(w.w, w.w);
            const uint64_t* xr = &xs2[k*XPAD + rh*4];
#pragma unroll
            for (int r = 0; r < 4; r++) {
                uint64_t xv = xr[r];
                fma2(acc[0][r], xv, w0);
                fma2(acc[1][r], xv, w1);
                fma2(acc[2][r], xv, w2);
                fma2(acc[3][r], xv, w3);
            }
        }
#pragma unroll
        for (int r = 0; r < 4; r++) {
            float2 v0 = upk(acc[0][r]);
            float2 v1 = upk(acc[1][r]);
            float2 v2 = upk(acc[2][r]);
            float2 v3 = upk(acc[3][r]);
            int rp = rh*4 + r;
            __half2 e0 = __floats2half2_rn(v0.x, v1.x);
            __half2 e1 = __floats2half2_rn(v2.x, v3.x);
            __half2 o0 = __floats2half2_rn(v0.y, v1.y);
            __half2 o1 = __floats2half2_rn(v2.y, v3.y);
            *(uint2*)&g_fth[((size_t)(nb0 + 2*rp))*FTC + cq*4]     = make_uint2(
                *(unsigned*)&e0, *(unsigned*)&e1);
            *(uint2*)&g_fth[((size_t)(nb0 + 2*rp + 1))*FTC + cq*4] = make_uint2(
                *(unsigned*)&o0, *(unsigned*)&o1);
        }
    }

    // res: thread owns col pair (2cr, 2cr+1), 2 row-pairs
    {
        int cr = t & 31;
        int rr = t >> 5;
        float2 bb = *(const float2*)&b_res[cr*2];
        uint64_t a0[2], a1[2];
        a0[0] = pk2(bb.x, bb.x); a0[1] = a0[0];
        a1[0] = pk2(bb.y, bb.y); a1[1] = a1[0];
        for (int k = 0; k < HIDD; k++) {
            float2 w = *(const float2*)&W_res[k*HIDD + cr*2];
            uint64_t w0 = pk2(w.x, w.x);
            uint64_t w1 = pk2(w.y, w.y);
            const uint64_t* xr = &xs2[k*XPAD + rr*2];
            fma2(a0[0], xr[0], w0); fma2(a1[0], xr[0], w1);
            fma2(a0[1], xr[1], w0); fma2(a1[1], xr[1], w1);
        }
#pragma unroll
        for (int i = 0; i < 2; i++) {
            float2 va = upk(a0[i]);
            float2 vb = upk(a1[i]);
            int rp = rr*2 + i;
            *(float2*)&g_res[(size_t)(nb0 + 2*rp)*HIDD + cr*2]     = make_float2(va.x, vb.x);
            *(float2*)&g_res[(size_t)(nb0 + 2*rp + 1)*HIDD + cr*2] = make_float2(va.y, vb.y);
        }
    }

    // el/er
    {
        int r = t >> 3, q = t & 7;
        const float* xf = (const float*)xs2;
        float s = 0.f;
        for (int k = 0; k < HIDD; k++)
            s += xf[k*(2*XPAD) + r] * Ps[k*8 + q];
        int nb = nb0 + r;
        if (q < 4) g_el[nb*4 + q]       = s;
        else       g_er[nb*4 + (q - 4)] = s;
    }
}

// ---------------- fused node-centric GAT aggregation + update (+ optional decoder) ----------------
// one warp per dst node, both batches. Per 32-edge window: all scattered el-loads
// and exps batched upfront into registers (MLP 8), then a pure shfl+gather+FMA loop.
__global__ void node_agg_k(const float* __restrict__ b_gat,
                           const float* __restrict__ W_dec, const float* __restrict__ b_dec,
                           float* __restrict__ out, int last) {
    int w = (blockIdx.x * blockDim.x + threadIdx.x) >> 5;
    int lane = threadIdx.x & 31;
    if (w >= Nn) return;
    int beg = g_rowptr[w];
    int end = beg + g_deg[w];

    int slot = lane >> 3;              // e-role: edge sub-slot (0..3)
    int bh   = lane & 7;               // e-role: (b,h)
    int b    = lane >> 4;              // gather role: batch
    int l16  = lane & 15;              // gather role: dim-quad

    float er_v = (lane < 8) ? g_er[w*8 + lane] : 0.f;
    float er_mine = __shfl_sync(0xffffffffu, er_v, bh);

    float zpart = 0.f;
    float4 acc[HEADS];
#pragma unroll
    for (int h = 0; h < HEADS; h++) acc[h] = make_float4(0.f, 0.f, 0.f, 0.f);

    for (int i0 = beg; i0 < end; i0 += 32) {
        int nE = end - i0; if (nE > 32) nE = 32;
        int sj = (i0 + lane < end) ? g_col[i0 + lane] : 0;

        // batch e-values: lane handles edges j = slot + 4k, its own bh
        float ereg[8];
#pragma unroll
        for (int k = 0; k < 8; k++) {
            int j = slot + 4*k;
            int s = __shfl_sync(0xffffffffu, sj, j);     // unconditional
            float e = 0.f;
            if (j < nE) {
                float v = g_el[s*8 + bh] + er_mine;
                v = v > 0.f ? v : SLOPE * v;
                e = __expf(v);
            }
            ereg[k] = e;
            zpart += e;
        }

        // FMA loop: pure shfl + coalesced fp16 gather + FMA
#pragma unroll
        for (int j = 0; j < 32; j++) {
            if (j >= nE) break;
            const int kk = j >> 2, sl2 = j & 3;
            int s = __shfl_sync(0xffffffffu, sj, j);
            float a0 = __shfl_sync(0xffffffffu, ereg[kk], sl2*8 + b*4 + 0);
            float a1 = __shfl_sync(0xffffffffu, ereg[kk], sl2*8 + b*4 + 1);
            float a2 = __shfl_sync(0xffffffffu, ereg[kk], sl2*8 + b*4 + 2);
            float a3 = __shfl_sync(0xffffffffu, ereg[kk], sl2*8 + b*4 + 3);
            const uint2* f = (const uint2*)&g_fth[((size_t)(s*2 + b))*FTC];
            uint2 u0 = f[l16];
            uint2 u1 = f[16 + l16];
            uint2 u2 = f[32 + l16];
            uint2 u3 = f[48 + l16];
            float2 p, q;
            p = __half22float2(*(__half2*)&u0.x); q = __half22float2(*(__half2*)&u0.y);
            acc[0].x += a0*p.x; acc[0].y += a0*p.y; acc[0].z += a0*q.x; acc[0].w += a0*q.y;
            p = __half22float2(*(__half2*)&u1.x); q = __half22float2(*(__half2*)&u1.y);
            acc[1].x += a1*p.x; acc[1].y += a1*p.y; acc[1].z += a1*q.x; acc[1].w += a1*q.y;
            p = __half22float2(*(__half2*)&u2.x); q = __half22float2(*(__half2*)&u2.y);
            acc[2].x += a2*p.x; acc[2].y += a2*p.y; acc[2].z += a2*q.x; acc[2].w += a2*q.y;
            p = __half22float2(*(__half2*)&u3.x); q = __half22float2(*(__half2*)&u3.y);
            acc[3].x += a3*p.x; acc[3].y += a3*p.y; acc[3].z += a3*q.x; acc[3].w += a3*q.y;
        }
    }

    // z reduce: sum over the 4 edge sub-slots -> lane holds z for its bh
    zpart += __shfl_xor_sync(0xffffffffu, zpart, 8);
    zpart += __shfl_xor_sync(0xffffffffu, zpart, 16);

    // normalize + head-mean
    float4 o = make_float4(0.f, 0.f, 0.f, 0.f);
#pragma unroll
    for (int h = 0; h < HEADS; h++) {
        float zh = __shfl_sync(0xffffffffu, zpart, b*4 + h);
        float rz = (zh > 0.f) ? 0.25f / zh : 0.f;
        o.x += acc[h].x * rz; o.y += acc[h].y * rz;
        o.z += acc[h].z * rz; o.w += acc[h].w * rz;
    }

    // epilogue: + mean_h(b_gat) + res, ELU
    int d0 = l16 * 4;
    const float4* bg = (const float4*)b_gat;
    float4 b0 = bg[l16], b1 = bg[16 + l16], b2 = bg[32 + l16], b3 = bg[48 + l16];
    float4 bgm;
    bgm.x = 0.25f*(b0.x + b1.x + b2.x + b3.x);
    bgm.y = 0.25f*(b0.y + b1.y + b2.y + b3.y);
    bgm.z = 0.25f*(b0.z + b1.z + b2.z + b3.z);
    bgm.w = 0.25f*(b0.w + b1.w + b2.w + b3.w);

    float4 rv = *(const float4*)&g_res[((size_t)(w*2 + b))*HIDD + d0];
    float ox = o.x + bgm.x + rv.x;
    float oy = o.y + bgm.y + rv.y;
    float oz = o.z + bgm.z + rv.z;
    float ow = o.w + bgm.w + rv.w;
    ox = ox > 0.f ? ox : expm1f(ox);
    oy = oy > 0.f ? oy : expm1f(oy);
    oz = oz > 0.f ? oz : expm1f(oz);
    ow = ow > 0.f ? ow : expm1f(ow);

    if (!last) {
        *(float4*)&g_x[((size_t)(w*2 + b))*HIDD + d0] = make_float4(ox, oy, oz, ow);
    } else {
        // fused decoder: out[b, w, :] = x[w, b, :] @ W_dec + b_dec
        float po[OUTD];
        const float4* W0 = (const float4*)&W_dec[(d0 + 0)*OUTD];
        const float4* W1 = (const float4*)&W_dec[(d0 + 1)*OUTD];
        const float4* W2 = (const float4*)&W_dec[(d0 + 2)*OUTD];
        const float4* W3 = (const float4*)&W_dec[(d0 + 3)*OUTD];
        float4 wa, wb;
        wa = W0[0]; wb = W0[1];
        po[0] = ox*wa.x; po[1] = ox*wa.y; po[2] = ox*wa.z; po[3] = ox*wa.w;
        po[4] = ox*wb.x; po[5] = ox*wb.y; po[6] = ox*wb.z; po[7] = ox*wb.w;
        wa = W1[0]; wb = W1[1];
        po[0] += oy*wa.x; po[1] += oy*wa.y; po[2] += oy*wa.z; po[3] += oy*wa.w;
        po[4] += oy*wb.x; po[5] += oy*wb.y; po[6] += oy*wb.z; po[7] += oy*wb.w;
        wa = W2[0]; wb = W2[1];
        po[0] += oz*wa.x; po[1] += oz*wa.y; po[2] += oz*wa.z; po[3] += oz*wa.w;
        po[4] += oz*wb.x; po[5] += oz*wb.y; po[6] += oz*wb.z; po[7] += oz*wb.w;
        wa = W3[0]; wb = W3[1];
        po[0] += ow*wa.x; po[1] += ow*wa.y; po[2] += ow*wa.z; po[3] += ow*wa.w;
        po[4] += ow*wb.x; po[5] += ow*wb.y; po[6] += ow*wb.z; po[7] += ow*wb.w;
#pragma unroll
        for (int off = 1; off < 16; off <<= 1)
#pragma unroll
            for (int oo = 0; oo < OUTD; oo++)
                po[oo] += __shfl_xor_sync(0xffffffffu, po[oo], off);
        if (l16 == 0) {
            float* op = &out[((size_t)b*Nn + w)*OUTD];
            float4 v0 = make_float4(po[0] + b_dec[0], po[1] + b_dec[1],
                                    po[2] + b_dec[2], po[3] + b_dec[3]);
            float4 v1 = make_float4(po[4] + b_dec[4], po[5] + b_dec[5],
                                    po[6] + b_dec[6], po[7] + b_dec[7]);
            *(float4*)&op[0] = v0;
            *(float4*)&op[4] = v1;
        }
    }
}

extern "C" void kernel_launch(void* const* d_in, const int* in_sizes, int n_in,
                              void* d_out, int out_size) {
    const float* h     = (const float*)d_in[0];
    const int*   ei    = (const int*)  d_in[1];
    const float* W_enc = (const float*)d_in[2];
    const float* b_enc = (const float*)d_in[3];
    const float* W_gat = (const float*)d_in[4];
    const float* a_l   = (const float*)d_in[5];
    const float* a_r   = (const float*)d_in[6];
    const float* b_gat = (const float*)d_in[7];
    const float* W_res = (const float*)d_in[8];
    const float* b_res = (const float*)d_in[9];
    const float* W_dec = (const float*)d_in[10];
    const float* b_dec = (const float*)d_in[11];
    float* out = (float*)d_out;

    // CSR build (every call; graph-replay safe)
    zero_k<<<(Nn + 255)/256, 256>>>();
    hist_k<<<(Ee + 255)/256, 256>>>(ei);
    alloc_k<<<(Nn + 255)/256, 256>>>();
    fill_k<<<(Ee + 255)/256, 256>>>(ei);

    proj_k<<<1, 512>>>(W_gat, a_l, a_r);
    enc_k<<<(NB*HIDD + 255)/256, 256>>>(h, W_enc, b_enc);

    for (int it = 0; it < 2; ++it) {
        ft_k<<<NB/FTROWS, 256>>>(W_gat, W_res, b_res);
        node_agg_k<<<(Nn*32 + 255)/256, 256>>>(b_gat, W_dec, b_dec, out, it == 1);
    }
}